// round 15
// baseline (speedup 1.0000x reference)
#include <cuda_runtime.h>
#include <cuda_fp16.h>
#include <math.h>
#include <stdint.h>

// ------------------------------------------------------------------
// Problem constants
// ------------------------------------------------------------------
#define BB 128          // batch (GEMM M)
#define SS 512          // sequence length
#define II 256          // input size
#define HH 1024         // hidden size
#define NC 10           // classes
#define KTOT 1280       // K = HH + II
#define NTOT 4096       // 4*HH gate columns

#define NCTA 128        // 2 batch-groups x 64 n-tiles, persistent
#define NTHREADS 256    // 8 warps: 4 in M x 2 in N
#define CTA_M 64        // batch rows per CTA
#define CTA_N 64        // gate columns per CTA
#define KC 128          // K elements per chunk
#define NCHUNK (KTOT / KC)   // 10 (2 x-chunks + 8 h-chunks)
#define NSTAGE 3

// Stage smem layout (bytes): Ah 16K | Al 16K | Bh 16K | Bl 16K = 64K
#define ST_AH 0
#define ST_AL 16384
#define ST_BH 32768
#define ST_BL 49152
#define STAGE_BYTES 65536
#define SMEM_NEED (NSTAGE * STAGE_BYTES)   // 192 KB -> 1 CTA/SM

// ------------------------------------------------------------------
// Persistent device scratch (allocation-free)
// ------------------------------------------------------------------
__device__ __align__(16) __half g_Whi[NTOT * KTOT];   // permuted [n'][k]
__device__ __align__(16) __half g_Wlo[NTOT * KTOT];
__device__ __align__(16) __half g_xhi[SS * BB * II];  // [s][b][i]
__device__ __align__(16) __half g_xlo[SS * BB * II];
__device__ __align__(16) __half g_hhi[2][BB * HH];
__device__ __align__(16) __half g_hlo[2][BB * HH];
__device__ float g_bias[NTOT];

// producer counters: g_prod[grp][hchunk] (hchunk = 128 h-cols), cumulative.
__device__ unsigned g_prod[2][8];
__device__ unsigned g_fin;

// ------------------------------------------------------------------
// PTX helpers (baseline compute_103 features only)
// ------------------------------------------------------------------
__device__ __forceinline__ uint32_t smem_u32(const void* p) {
    uint32_t a;
    asm("{ .reg .u64 t; cvta.to.shared.u64 t, %1; cvt.u32.u64 %0, t; }"
        : "=r"(a) : "l"(p));
    return a;
}
__device__ __forceinline__ void cp_async16(uint32_t saddr, const void* gaddr) {
    asm volatile("cp.async.cg.shared.global [%0], [%1], 16;"
                 :: "r"(saddr), "l"(gaddr) : "memory");
}
__device__ __forceinline__ void cp_commit() {
    asm volatile("cp.async.commit_group;" ::: "memory");
}
__device__ __forceinline__ void cp_wait1() {
    asm volatile("cp.async.wait_group 1;" ::: "memory");
}
__device__ __forceinline__ void cp_wait0() {
    asm volatile("cp.async.wait_group 0;" ::: "memory");
}
__device__ __forceinline__ void ldsm_x4(uint32_t* r, uint32_t addr) {
    asm volatile("ldmatrix.sync.aligned.m8n8.x4.shared.b16 {%0,%1,%2,%3}, [%4];"
                 : "=r"(r[0]), "=r"(r[1]), "=r"(r[2]), "=r"(r[3]) : "r"(addr));
}
__device__ __forceinline__ void mma16816(float* d, const uint32_t* a,
                                         uint32_t b0, uint32_t b1) {
    asm volatile(
        "mma.sync.aligned.m16n8k16.row.col.f32.f16.f16.f32 "
        "{%0,%1,%2,%3}, {%4,%5,%6,%7}, {%8,%9}, {%0,%1,%2,%3};"
        : "+f"(d[0]), "+f"(d[1]), "+f"(d[2]), "+f"(d[3])
        : "r"(a[0]), "r"(a[1]), "r"(a[2]), "r"(a[3]), "r"(b0), "r"(b1));
}
__device__ __forceinline__ unsigned ld_acq(const unsigned* p) {
    unsigned v;
    asm volatile("ld.acquire.gpu.global.u32 %0, [%1];"
                 : "=r"(v) : "l"(p) : "memory");
    return v;
}
__device__ __forceinline__ void red_release_add(unsigned* p, unsigned v) {
    asm volatile("red.release.gpu.global.add.u32 [%0], %1;"
                 :: "l"(p), "r"(v) : "memory");
}
// fast activations (MUFU-based); rel err ~1e-6, budget is 1e-3
__device__ __forceinline__ float sigmoidf_(float v) {
    return __fdividef(1.0f, 1.0f + __expf(-v));
}
__device__ __forceinline__ float tanhf_(float v) {
    return 1.0f - __fdividef(2.0f, 1.0f + __expf(2.0f * v));
}
// swizzled smem byte offset within a [rows][64 half] sub-tile (128B rows)
__device__ __forceinline__ uint32_t sw_off(int r, int c) {   // c = 16B chunk 0..7
    return (uint32_t)(r * 128 + ((c ^ (r & 7)) << 4));
}

// ------------------------------------------------------------------
// Prep kernels
// ------------------------------------------------------------------
__global__ void prep_weights(const float* __restrict__ W_ih,
                             const float* __restrict__ W_hh) {
    int idx = blockIdx.x * blockDim.x + threadIdx.x;
    if (idx >= NTOT * KTOT) return;
    int n = idx / KTOT;
    int k = idx - n * KTOT;
    int nb = n >> 6;
    int r6 = n & 63;
    int wn = r6 >> 5;
    int g = (r6 >> 3) & 3;
    int jj = r6 & 7;
    int row = g * HH + nb * 16 + wn * 8 + jj;
    float v = (k < HH) ? W_hh[row * HH + k] : W_ih[row * II + (k - HH)];
    __half hi = __float2half_rn(v);
    __half lo = __float2half_rn(v - __half2float(hi));
    g_Whi[idx] = hi;
    g_Wlo[idx] = lo;
}

__global__ void prep_x(const float* __restrict__ x) {
    int idx = blockIdx.x * blockDim.x + threadIdx.x;
    if (idx >= SS * BB * II) return;
    int s = idx / (BB * II);
    int r = idx - s * (BB * II);
    int b = r / II;
    int i = r - b * II;
    float v = x[(b * SS + s) * II + i];
    __half hi = __float2half_rn(v);
    __half lo = __float2half_rn(v - __half2float(hi));
    g_xhi[idx] = hi;
    g_xlo[idx] = lo;
}

__global__ void prep_state(const float* __restrict__ h0,
                           const float* __restrict__ b_ih,
                           const float* __restrict__ b_hh) {
    int idx = blockIdx.x * blockDim.x + threadIdx.x;
    if (idx < BB * HH) {
        float v = h0[idx];
        __half hi = __float2half_rn(v);
        __half lo = __float2half_rn(v - __half2float(hi));
        g_hhi[0][idx] = hi;
        g_hlo[0][idx] = lo;
    }
    if (idx < NTOT) g_bias[idx] = b_ih[idx] + b_hh[idx];
}

// ------------------------------------------------------------------
// Persistent LSTM kernel: all 512 steps. R12 structure, but the three
// split products accumulate into SEPARATE register banks so all 12
// MMAs per k-step are independent (accumulator reuse distance 4 -> 12
// issues, hiding HMMA fixed latency). Banks summed in the epilogue.
// ------------------------------------------------------------------
__global__ void __launch_bounds__(NTHREADS, 1) lstm_persistent(
    const float* __restrict__ c0in)
{
    extern __shared__ char smem_raw[];
    const uint32_t sb = smem_u32(smem_raw);

    const int tid = threadIdx.x;
    const int wid = tid >> 5;
    const int lane = tid & 31;
    const int grp = blockIdx.x & 1;        // batch group (rows grp*64..+63)
    const int nb = blockIdx.x >> 1;        // n-tile index (0..63)
    const int gb = grp * CTA_M;            // global batch base
    const int off = nb >> 3;               // own h-chunk first (producer = nb>>3)
    const int wm = wid & 3;                // 0..3 : M warp group (16 rows)
    const int wn = wid >> 2;               // 0..1 : N warp group (32 cols)
    const int frow = lane >> 2;            // fragment row 0..7
    const int fcol = (lane & 3) * 2;       // fragment col (even)
    const int b0 = gb + wm * 16 + frow;
    const int jbw = nb * 16 + wn * 8;      // h-column base for this warp

    float bias_r[4][2];
#pragma unroll
    for (int g = 0; g < 4; g++)
#pragma unroll
        for (int e = 0; e < 2; e++)
            bias_r[g][e] = g_bias[g * HH + jbw + fcol + e];

    float creg[4];
    creg[0] = c0in[b0 * HH + jbw + fcol];
    creg[1] = c0in[b0 * HH + jbw + fcol + 1];
    creg[2] = c0in[(b0 + 8) * HH + jbw + fcol];
    creg[3] = c0in[(b0 + 8) * HH + jbw + fcol + 1];

    // stage loader: ci 0,1 -> x chunks (ka 8,9) of step ss;
    //               ci 2..9 -> h chunks of step ss, ka=((ci-2)+off)&7
    auto load_stage = [&](int ci, int ss) {
        const uint32_t st = sb + (uint32_t)(ci % NSTAGE) * STAGE_BYTES;
        const int ka = (ci < 2) ? (8 + ci) : (((ci - 2) + off) & 7);
        const int k0 = ka * KC;
        const __half* __restrict__ hin_hi = g_hhi[ss & 1];
        const __half* __restrict__ hin_lo = g_hlo[ss & 1];
#pragma unroll
        for (int i = 0; i < 4; i++) {           // A: 64 x 128 halves
            int id = tid + i * NTHREADS;        // 0..1023
            int r = id >> 4;                    // local batch row 0..63
            int c = id & 15;                    // 16B chunk in 256B row
            uint32_t d = (uint32_t)((c >> 3) * 8192) + sw_off(r, c & 7);
            if (ka < 8) {
                cp_async16(st + ST_AH + d, hin_hi + (gb + r) * HH + k0 + c * 8);
                cp_async16(st + ST_AL + d, hin_lo + (gb + r) * HH + k0 + c * 8);
            } else {
                size_t o = ((size_t)ss * BB + gb + r) * II + (k0 - HH) + c * 8;
                cp_async16(st + ST_AH + d, g_xhi + o);
                cp_async16(st + ST_AL + d, g_xlo + o);
            }
        }
#pragma unroll
        for (int i = 0; i < 4; i++) {           // B: 64 x 128 halves
            int id = tid + i * NTHREADS;
            int r = id >> 4;
            int c = id & 15;
            uint32_t d = (uint32_t)((c >> 3) * 8192) + sw_off(r, c & 7);
            size_t o = (size_t)(nb * CTA_N + r) * KTOT + k0 + c * 8;
            cp_async16(st + ST_BH + d, g_Whi + o);
            cp_async16(st + ST_BL + d, g_Wlo + o);
        }
        cp_commit();
    };

    // prologue for step 0: x chunks (h0 published by prep, stream-ordered)
    load_stage(0, 0);
    load_stage(1, 0);

    for (int s = 0; s < SS; s++) {
        __half* __restrict__ hout_hi = g_hhi[(s & 1) ^ 1];
        __half* __restrict__ hout_lo = g_hlo[(s & 1) ^ 1];

        // all-thread acquire spin before reading an h-chunk of step s
        auto poll_chunk = [&](int ci) {
            if (s > 0) {
                const int ka = ((ci - 2) + off) & 7;
                const unsigned tgt = 8u * (unsigned)s;
                const unsigned* ctr = &g_prod[grp][ka];
                while (ld_acq(ctr) < tgt) __nanosleep(32);
            }
        };

        // three independent accumulator banks (hi*hi, hi*lo, lo*hi)
        float accA[4][4], accB[4][4], accC[4][4];
#pragma unroll
        for (int g = 0; g < 4; g++)
#pragma unroll
            for (int e = 0; e < 4; e++) {
                accA[g][e] = 0.0f;
                accB[g][e] = 0.0f;
                accC[g][e] = 0.0f;
            }

        for (int i = 0; i < NCHUNK; i++) {
            if (i == NCHUNK - 1) cp_wait0(); else cp_wait1();
            __syncthreads();               // the ONLY barrier per chunk

            const uint32_t st = sb + (uint32_t)(i % NSTAGE) * STAGE_BYTES;
#pragma unroll
            for (int kk = 0; kk < KC; kk += 16) {
                const uint32_t subo = (uint32_t)((kk >> 6) * 8192);
                const int ck = (((kk & 63) >> 3)) + (lane >> 4);
                const int ra = wm * 16 + (lane & 15);
                const int rb = wn * 32 + (lane & 15);
                uint32_t ah[4], al[4], bh0[4], bh1[4], bl0[4], bl1[4];
                ldsm_x4(ah, st + ST_AH + subo + sw_off(ra, ck));
                ldsm_x4(al, st + ST_AL + subo + sw_off(ra, ck));
                ldsm_x4(bh0, st + ST_BH + subo + sw_off(rb, ck));
                ldsm_x4(bh1, st + ST_BH + subo + sw_off(rb + 16, ck));
                ldsm_x4(bl0, st + ST_BL + subo + sw_off(rb, ck));
                ldsm_x4(bl1, st + ST_BL + subo + sw_off(rb + 16, ck));

                // 12 mutually independent MMAs (distinct accumulators)
                mma16816(accA[0], ah, bh0[0], bh0[2]);   // hi*hi
                mma16816(accA[1], ah, bh0[1], bh0[3]);
                mma16816(accA[2], ah, bh1[0], bh1[2]);
                mma16816(accA[3], ah, bh1[1], bh1[3]);
                mma16816(accB[0], ah, bl0[0], bl0[2]);   // hi*lo
                mma16816(accB[1], ah, bl0[1], bl0[3]);
                mma16816(accB[2], ah, bl1[0], bl1[2]);
                mma16816(accB[3], ah, bl1[1], bl1[3]);
                mma16816(accC[0], al, bh0[0], bh0[2]);   // lo*hi
                mma16816(accC[1], al, bh0[1], bh0[3]);
                mma16816(accC[2], al, bh1[0], bh1[2]);
                mma16816(accC[3], al, bh1[1], bh1[3]);
            }

            // issue next chunk's loads (spin stalls only this thread's issue)
            if (i + 2 < NCHUNK) {
                poll_chunk(i + 2);         // i+2 >= 2: always an h-chunk
                load_stage(i + 2, s);
            }
        }

        // ---- prefetch next step's x chunks while epilogue computes ----
        if (s + 1 < SS) {
            load_stage(0, s + 1);
            load_stage(1, s + 1);
        }

        // ---- register-only LSTM cell update (sum the three banks) ----
#pragma unroll
        for (int e = 0; e < 4; e++) {
            float iv = accA[0][e] + accB[0][e] + accC[0][e] + bias_r[0][e & 1];
            float fv = accA[1][e] + accB[1][e] + accC[1][e] + bias_r[1][e & 1];
            float gv = accA[2][e] + accB[2][e] + accC[2][e] + bias_r[2][e & 1];
            float ov = accA[3][e] + accB[3][e] + accC[3][e] + bias_r[3][e & 1];
            float ig = sigmoidf_(iv);
            float fg = sigmoidf_(fv);
            float gg = tanhf_(gv);
            float og = sigmoidf_(ov);
            float cn = fg * creg[e] + ig * gg;
            creg[e] = cn;
            float hn = og * tanhf_(cn);
            int b = b0 + ((e >> 1) << 3);
            int idx = b * HH + jbw + fcol + (e & 1);
            __half hi = __float2half_rn(hn);
            hout_hi[idx] = hi;
            hout_lo[idx] = __float2half_rn(hn - __half2float(hi));
        }

        // ---- publish: release-atomic arrive on this CTA's h-chunk ----
        __syncthreads();                 // all h stores of this CTA done
        if (tid == 0) {
            red_release_add(&g_prod[grp][nb >> 3], 1u);
        }
    }

    // ---- finish: reset counters for the next graph replay ----
    if (tid == 0) {
        __threadfence();
        atomicAdd(&g_fin, 1u);
    }
    if (blockIdx.x == 0 && tid == 0) {
        while (ld_acq(&g_fin) < (unsigned)NCTA) __nanosleep(64);
#pragma unroll
        for (int g2 = 0; g2 < 2; g2++)
#pragma unroll
            for (int kc = 0; kc < 8; kc++)
                *((volatile unsigned*)&g_prod[g2][kc]) = 0u;
        *((volatile unsigned*)&g_fin) = 0u;
        __threadfence();
    }
}

// ------------------------------------------------------------------
// Head: out[b,c] = h_last . W_out[c] + b_out[c]
// ------------------------------------------------------------------
__global__ void head_kernel(const float* __restrict__ W_out,
                            const float* __restrict__ b_out,
                            float* __restrict__ out) {
    int b = blockIdx.x;
    int c = blockIdx.y;
    int lane = threadIdx.x;
    const __half* hh = g_hhi[0] + b * HH;   // 512 steps even -> buffer 0
    const __half* hl = g_hlo[0] + b * HH;
    const float* w = W_out + c * HH;
    float sum = 0.0f;
    for (int k = lane; k < HH; k += 32) {
        float h = __half2float(hh[k]) + __half2float(hl[k]);
        sum = fmaf(h, w[k], sum);
    }
#pragma unroll
    for (int off = 16; off > 0; off >>= 1)
        sum += __shfl_down_sync(0xFFFFFFFFu, sum, off);
    if (lane == 0) out[b * NC + c] = sum + b_out[c];
}

// ------------------------------------------------------------------
// Host
// ------------------------------------------------------------------
extern "C" void kernel_launch(void* const* d_in, const int* in_sizes, int n_in,
                              void* d_out, int out_size) {
    const float* x     = (const float*)d_in[0];
    const float* h0    = (const float*)d_in[1];
    const float* c0    = (const float*)d_in[2];
    const float* W_ih  = (const float*)d_in[3];
    const float* W_hh  = (const float*)d_in[4];
    const float* b_ih  = (const float*)d_in[5];
    const float* b_hh  = (const float*)d_in[6];
    const float* W_out = (const float*)d_in[7];
    const float* b_out = (const float*)d_in[8];
    float* out = (float*)d_out;

    cudaFuncSetAttribute(lstm_persistent,
                         cudaFuncAttributeMaxDynamicSharedMemorySize, SMEM_NEED);

    prep_weights<<<(NTOT * KTOT + 255) / 256, 256>>>(W_ih, W_hh);
    prep_x<<<(SS * BB * II + 255) / 256, 256>>>(x);
    prep_state<<<(BB * HH + 255) / 256, 256>>>(h0, b_ih, b_hh);

    lstm_persistent<<<NCTA, NTHREADS, SMEM_NEED>>>(c0);

    head_kernel<<<dim3(BB, NC), 32>>>(W_out, b_out, out);
}

// round 16
// speedup vs baseline: 1.9420x; 1.9420x over previous
#include <cuda_runtime.h>
#include <cuda_fp16.h>
#include <math.h>
#include <stdint.h>

// ------------------------------------------------------------------
// Problem constants
// ------------------------------------------------------------------
#define BB 128          // batch (GEMM M)
#define SS 512          // sequence length
#define II 256          // input size
#define HH 1024         // hidden size
#define NC 10           // classes
#define KTOT 1280       // K = HH + II
#define NTOT 4096       // 4*HH gate columns

#define NCTA 128        // 2 batch-groups x 64 n-tiles, persistent
#define NTHREADS 256    // 8 warps: 4 in M x 2 in N
#define CTA_M 64        // batch rows per CTA
#define CTA_N 64        // gate columns per CTA
#define KC 128          // K elements per chunk
#define NCHUNK (KTOT / KC)   // 10 (2 x-chunks + 8 h-chunks)
#define NSTAGE 3

// Stage smem layout (bytes): Ah 16K | Al 16K | Bh 16K = 48K
// (W-lo term dropped: weights use rounded-fp16 Wh only; h split exact)
#define ST_AH 0
#define ST_AL 16384
#define ST_BH 32768
#define STAGE_BYTES 49152
#define SMEM_NEED (NSTAGE * STAGE_BYTES)   // 144 KB -> 1 CTA/SM

// ------------------------------------------------------------------
// Persistent device scratch (allocation-free)
// ------------------------------------------------------------------
__device__ __align__(16) __half g_Whi[NTOT * KTOT];   // permuted [n'][k], fp16-rounded
__device__ __align__(16) __half g_xhi[SS * BB * II];  // [s][b][i] hi
__device__ __align__(16) __half g_xlo[SS * BB * II];  // [s][b][i] lo
__device__ __align__(16) __half g_hhi[2][BB * HH];
__device__ __align__(16) __half g_hlo[2][BB * HH];
__device__ float g_bias[NTOT];

// producer counters: g_prod[grp][hchunk] (hchunk = 128 h-cols), cumulative.
__device__ unsigned g_prod[2][8];
__device__ unsigned g_fin;

// ------------------------------------------------------------------
// PTX helpers (baseline compute_103 features only)
// ------------------------------------------------------------------
__device__ __forceinline__ uint32_t smem_u32(const void* p) {
    uint32_t a;
    asm("{ .reg .u64 t; cvta.to.shared.u64 t, %1; cvt.u32.u64 %0, t; }"
        : "=r"(a) : "l"(p));
    return a;
}
__device__ __forceinline__ void cp_async16(uint32_t saddr, const void* gaddr) {
    asm volatile("cp.async.cg.shared.global [%0], [%1], 16;"
                 :: "r"(saddr), "l"(gaddr) : "memory");
}
__device__ __forceinline__ void cp_commit() {
    asm volatile("cp.async.commit_group;" ::: "memory");
}
__device__ __forceinline__ void cp_wait1() {
    asm volatile("cp.async.wait_group 1;" ::: "memory");
}
__device__ __forceinline__ void cp_wait0() {
    asm volatile("cp.async.wait_group 0;" ::: "memory");
}
__device__ __forceinline__ void ldsm_x4(uint32_t* r, uint32_t addr) {
    asm volatile("ldmatrix.sync.aligned.m8n8.x4.shared.b16 {%0,%1,%2,%3}, [%4];"
                 : "=r"(r[0]), "=r"(r[1]), "=r"(r[2]), "=r"(r[3]) : "r"(addr));
}
__device__ __forceinline__ void mma16816(float* d, const uint32_t* a,
                                         uint32_t b0, uint32_t b1) {
    asm volatile(
        "mma.sync.aligned.m16n8k16.row.col.f32.f16.f16.f32 "
        "{%0,%1,%2,%3}, {%4,%5,%6,%7}, {%8,%9}, {%0,%1,%2,%3};"
        : "+f"(d[0]), "+f"(d[1]), "+f"(d[2]), "+f"(d[3])
        : "r"(a[0]), "r"(a[1]), "r"(a[2]), "r"(a[3]), "r"(b0), "r"(b1));
}
__device__ __forceinline__ unsigned ld_acq(const unsigned* p) {
    unsigned v;
    asm volatile("ld.acquire.gpu.global.u32 %0, [%1];"
                 : "=r"(v) : "l"(p) : "memory");
    return v;
}
__device__ __forceinline__ void red_release_add(unsigned* p, unsigned v) {
    asm volatile("red.release.gpu.global.add.u32 [%0], %1;"
                 :: "l"(p), "r"(v) : "memory");
}
// fast activations (MUFU-based); rel err ~1e-6, budget is 1e-3
__device__ __forceinline__ float sigmoidf_(float v) {
    return __fdividef(1.0f, 1.0f + __expf(-v));
}
__device__ __forceinline__ float tanhf_(float v) {
    return 1.0f - __fdividef(2.0f, 1.0f + __expf(2.0f * v));
}
// swizzled smem byte offset within a [rows][64 half] sub-tile (128B rows)
__device__ __forceinline__ uint32_t sw_off(int r, int c) {   // c = 16B chunk 0..7
    return (uint32_t)(r * 128 + ((c ^ (r & 7)) << 4));
}

// ------------------------------------------------------------------
// Prep kernels
// ------------------------------------------------------------------
__global__ void prep_weights(const float* __restrict__ W_ih,
                             const float* __restrict__ W_hh) {
    int idx = blockIdx.x * blockDim.x + threadIdx.x;
    if (idx >= NTOT * KTOT) return;
    int n = idx / KTOT;
    int k = idx - n * KTOT;
    int nb = n >> 6;
    int r6 = n & 63;
    int wn = r6 >> 5;
    int g = (r6 >> 3) & 3;
    int jj = r6 & 7;
    int row = g * HH + nb * 16 + wn * 8 + jj;
    float v = (k < HH) ? W_hh[row * HH + k] : W_ih[row * II + (k - HH)];
    g_Whi[idx] = __float2half_rn(v);
}

__global__ void prep_x(const float* __restrict__ x) {
    int idx = blockIdx.x * blockDim.x + threadIdx.x;
    if (idx >= SS * BB * II) return;
    int s = idx / (BB * II);
    int r = idx - s * (BB * II);
    int b = r / II;
    int i = r - b * II;
    float v = x[(b * SS + s) * II + i];
    __half hi = __float2half_rn(v);
    __half lo = __float2half_rn(v - __half2float(hi));
    g_xhi[idx] = hi;
    g_xlo[idx] = lo;
}

__global__ void prep_state(const float* __restrict__ h0,
                           const float* __restrict__ b_ih,
                           const float* __restrict__ b_hh) {
    int idx = blockIdx.x * blockDim.x + threadIdx.x;
    if (idx < BB * HH) {
        float v = h0[idx];
        __half hi = __float2half_rn(v);
        __half lo = __float2half_rn(v - __half2float(hi));
        g_hhi[0][idx] = hi;
        g_hlo[0][idx] = lo;
    }
    if (idx < NTOT) g_bias[idx] = b_ih[idx] + b_hh[idx];
}

// ------------------------------------------------------------------
// Persistent LSTM kernel: all 512 steps. R12 structure, 2-term split:
//   gates = hh*Wh + hl*Wh  (= exact h times fp16-rounded W)
// 8 MMAs + 4 LDSM per k-step (was 12 + 6): -33% on the issue-bound path.
// ------------------------------------------------------------------
__global__ void __launch_bounds__(NTHREADS, 1) lstm_persistent(
    const float* __restrict__ c0in)
{
    extern __shared__ char smem_raw[];
    const uint32_t sb = smem_u32(smem_raw);

    const int tid = threadIdx.x;
    const int wid = tid >> 5;
    const int lane = tid & 31;
    const int grp = blockIdx.x & 1;        // batch group (rows grp*64..+63)
    const int nb = blockIdx.x >> 1;        // n-tile index (0..63)
    const int gb = grp * CTA_M;            // global batch base
    const int off = nb >> 3;               // own h-chunk first (producer = nb>>3)
    const int wm = wid & 3;                // 0..3 : M warp group (16 rows)
    const int wn = wid >> 2;               // 0..1 : N warp group (32 cols)
    const int frow = lane >> 2;            // fragment row 0..7
    const int fcol = (lane & 3) * 2;       // fragment col (even)
    const int b0 = gb + wm * 16 + frow;
    const int jbw = nb * 16 + wn * 8;      // h-column base for this warp

    float bias_r[4][2];
#pragma unroll
    for (int g = 0; g < 4; g++)
#pragma unroll
        for (int e = 0; e < 2; e++)
            bias_r[g][e] = g_bias[g * HH + jbw + fcol + e];

    float creg[4];
    creg[0] = c0in[b0 * HH + jbw + fcol];
    creg[1] = c0in[b0 * HH + jbw + fcol + 1];
    creg[2] = c0in[(b0 + 8) * HH + jbw + fcol];
    creg[3] = c0in[(b0 + 8) * HH + jbw + fcol + 1];

    // stage loader: ci 0,1 -> x chunks (ka 8,9) of step ss;
    //               ci 2..9 -> h chunks of step ss, ka=((ci-2)+off)&7
    auto load_stage = [&](int ci, int ss) {
        const uint32_t st = sb + (uint32_t)(ci % NSTAGE) * STAGE_BYTES;
        const int ka = (ci < 2) ? (8 + ci) : (((ci - 2) + off) & 7);
        const int k0 = ka * KC;
        const __half* __restrict__ hin_hi = g_hhi[ss & 1];
        const __half* __restrict__ hin_lo = g_hlo[ss & 1];
#pragma unroll
        for (int i = 0; i < 4; i++) {           // A: 64 x 128 halves (hi+lo)
            int id = tid + i * NTHREADS;        // 0..1023
            int r = id >> 4;                    // local batch row 0..63
            int c = id & 15;                    // 16B chunk in 256B row
            uint32_t d = (uint32_t)((c >> 3) * 8192) + sw_off(r, c & 7);
            if (ka < 8) {
                cp_async16(st + ST_AH + d, hin_hi + (gb + r) * HH + k0 + c * 8);
                cp_async16(st + ST_AL + d, hin_lo + (gb + r) * HH + k0 + c * 8);
            } else {
                size_t o = ((size_t)ss * BB + gb + r) * II + (k0 - HH) + c * 8;
                cp_async16(st + ST_AH + d, g_xhi + o);
                cp_async16(st + ST_AL + d, g_xlo + o);
            }
        }
#pragma unroll
        for (int i = 0; i < 4; i++) {           // B: 64 x 128 halves (hi only)
            int id = tid + i * NTHREADS;
            int r = id >> 4;
            int c = id & 15;
            uint32_t d = (uint32_t)((c >> 3) * 8192) + sw_off(r, c & 7);
            size_t o = (size_t)(nb * CTA_N + r) * KTOT + k0 + c * 8;
            cp_async16(st + ST_BH + d, g_Whi + o);
        }
        cp_commit();
    };

    // prologue for step 0: x chunks (h0 published by prep, stream-ordered)
    load_stage(0, 0);
    load_stage(1, 0);

    for (int s = 0; s < SS; s++) {
        __half* __restrict__ hout_hi = g_hhi[(s & 1) ^ 1];
        __half* __restrict__ hout_lo = g_hlo[(s & 1) ^ 1];

        // all-thread acquire spin before reading an h-chunk of step s
        auto poll_chunk = [&](int ci) {
            if (s > 0) {
                const int ka = ((ci - 2) + off) & 7;
                const unsigned tgt = 8u * (unsigned)s;
                const unsigned* ctr = &g_prod[grp][ka];
                while (ld_acq(ctr) < tgt) __nanosleep(32);
            }
        };

        float acc[4][4];
#pragma unroll
        for (int g = 0; g < 4; g++)
#pragma unroll
            for (int e = 0; e < 4; e++) acc[g][e] = 0.0f;

        for (int i = 0; i < NCHUNK; i++) {
            if (i == NCHUNK - 1) cp_wait0(); else cp_wait1();
            __syncthreads();               // the ONLY barrier per chunk

            const uint32_t st = sb + (uint32_t)(i % NSTAGE) * STAGE_BYTES;
#pragma unroll
            for (int kk = 0; kk < KC; kk += 16) {
                const uint32_t subo = (uint32_t)((kk >> 6) * 8192);
                const int ck = (((kk & 63) >> 3)) + (lane >> 4);
                const int ra = wm * 16 + (lane & 15);
                const int rb = wn * 32 + (lane & 15);
                uint32_t ah[4], al[4], bh0[4], bh1[4];
                ldsm_x4(ah, st + ST_AH + subo + sw_off(ra, ck));
                ldsm_x4(al, st + ST_AL + subo + sw_off(ra, ck));
                ldsm_x4(bh0, st + ST_BH + subo + sw_off(rb, ck));
                ldsm_x4(bh1, st + ST_BH + subo + sw_off(rb + 16, ck));

                mma16816(acc[0], ah, bh0[0], bh0[2]);   // hh * Wh
                mma16816(acc[1], ah, bh0[1], bh0[3]);
                mma16816(acc[2], ah, bh1[0], bh1[2]);
                mma16816(acc[3], ah, bh1[1], bh1[3]);
                mma16816(acc[0], al, bh0[0], bh0[2]);   // hl * Wh
                mma16816(acc[1], al, bh0[1], bh0[3]);
                mma16816(acc[2], al, bh1[0], bh1[2]);
                mma16816(acc[3], al, bh1[1], bh1[3]);
            }

            // issue next chunk's loads (spin stalls only this thread's issue)
            if (i + 2 < NCHUNK) {
                poll_chunk(i + 2);         // i+2 >= 2: always an h-chunk
                load_stage(i + 2, s);
            }
        }

        // ---- prefetch next step's x chunks while epilogue computes ----
        if (s + 1 < SS) {
            load_stage(0, s + 1);
            load_stage(1, s + 1);
        }

        // ---- register-only LSTM cell update ----
#pragma unroll
        for (int e = 0; e < 4; e++) {
            float iv = acc[0][e] + bias_r[0][e & 1];
            float fv = acc[1][e] + bias_r[1][e & 1];
            float gv = acc[2][e] + bias_r[2][e & 1];
            float ov = acc[3][e] + bias_r[3][e & 1];
            float ig = sigmoidf_(iv);
            float fg = sigmoidf_(fv);
            float gg = tanhf_(gv);
            float og = sigmoidf_(ov);
            float cn = fg * creg[e] + ig * gg;
            creg[e] = cn;
            float hn = og * tanhf_(cn);
            int b = b0 + ((e >> 1) << 3);
            int idx = b * HH + jbw + fcol + (e & 1);
            __half hi = __float2half_rn(hn);
            hout_hi[idx] = hi;
            hout_lo[idx] = __float2half_rn(hn - __half2float(hi));
        }

        // ---- publish: release-atomic arrive on this CTA's h-chunk ----
        __syncthreads();                 // all h stores of this CTA done
        if (tid == 0) {
            red_release_add(&g_prod[grp][nb >> 3], 1u);
        }
    }

    // ---- finish: reset counters for the next graph replay ----
    if (tid == 0) {
        __threadfence();
        atomicAdd(&g_fin, 1u);
    }
    if (blockIdx.x == 0 && tid == 0) {
        while (ld_acq(&g_fin) < (unsigned)NCTA) __nanosleep(64);
#pragma unroll
        for (int g2 = 0; g2 < 2; g2++)
#pragma unroll
            for (int kc = 0; kc < 8; kc++)
                *((volatile unsigned*)&g_prod[g2][kc]) = 0u;
        *((volatile unsigned*)&g_fin) = 0u;
        __threadfence();
    }
}

// ------------------------------------------------------------------
// Head: out[b,c] = h_last . W_out[c] + b_out[c]
// ------------------------------------------------------------------
__global__ void head_kernel(const float* __restrict__ W_out,
                            const float* __restrict__ b_out,
                            float* __restrict__ out) {
    int b = blockIdx.x;
    int c = blockIdx.y;
    int lane = threadIdx.x;
    const __half* hh = g_hhi[0] + b * HH;   // 512 steps even -> buffer 0
    const __half* hl = g_hlo[0] + b * HH;
    const float* w = W_out + c * HH;
    float sum = 0.0f;
    for (int k = lane; k < HH; k += 32) {
        float h = __half2float(hh[k]) + __half2float(hl[k]);
        sum = fmaf(h, w[k], sum);
    }
#pragma unroll
    for (int off = 16; off > 0; off >>= 1)
        sum += __shfl_down_sync(0xFFFFFFFFu, sum, off);
    if (lane == 0) out[b * NC + c] = sum + b_out[c];
}

// ------------------------------------------------------------------
// Host
// ------------------------------------------------------------------
extern "C" void kernel_launch(void* const* d_in, const int* in_sizes, int n_in,
                              void* d_out, int out_size) {
    const float* x     = (const float*)d_in[0];
    const float* h0    = (const float*)d_in[1];
    const float* c0    = (const float*)d_in[2];
    const float* W_ih  = (const float*)d_in[3];
    const float* W_hh  = (const float*)d_in[4];
    const float* b_ih  = (const float*)d_in[5];
    const float* b_hh  = (const float*)d_in[6];
    const float* W_out = (const float*)d_in[7];
    const float* b_out = (const float*)d_in[8];
    float* out = (float*)d_out;

    cudaFuncSetAttribute(lstm_persistent,
                         cudaFuncAttributeMaxDynamicSharedMemorySize, SMEM_NEED);

    prep_weights<<<(NTOT * KTOT + 255) / 256, 256>>>(W_ih, W_hh);
    prep_x<<<(SS * BB * II + 255) / 256, 256>>>(x);
    prep_state<<<(BB * HH + 255) / 256, 256>>>(h0, b_ih, b_hh);

    lstm_persistent<<<NCTA, NTHREADS, SMEM_NEED>>>(c0);

    head_kernel<<<dim3(BB, NC), 32>>>(W_out, b_out, out);
}

// round 17
// speedup vs baseline: 2.6569x; 1.3682x over previous
#include <cuda_runtime.h>
#include <cuda_fp16.h>
#include <math.h>
#include <stdint.h>

// ------------------------------------------------------------------
// Problem constants
// ------------------------------------------------------------------
#define BB 128          // batch (GEMM M)
#define SS 512          // sequence length
#define II 256          // input size
#define HH 1024         // hidden size
#define NC 10           // classes
#define KTOT 1280       // K = HH + II
#define NTOT 4096       // 4*HH gate columns

#define NCTA 128        // 2 batch-groups x 64 n-tiles, persistent
#define NTHREADS 256    // 8 warps: 4 in M x 2 in N
#define CTA_M 64        // batch rows per CTA
#define CTA_N 64        // gate columns per CTA
#define KC 128          // K elements per chunk
#define NCHUNK (KTOT / KC)   // 10 (2 x-chunks + 8 h-chunks)
#define NSTAGE 3

// Stage smem layout (bytes): Ah 16K | Bh 16K = 32K
// Pure fp16 operands (fp32 accumulate); all lo-residual terms dropped.
#define ST_AH 0
#define ST_BH 16384
#define STAGE_BYTES 32768
#define SMEM_NEED (NSTAGE * STAGE_BYTES)   // 96 KB (keep 1 CTA/SM via launch_bounds)

// ------------------------------------------------------------------
// Persistent device scratch (allocation-free)
// ------------------------------------------------------------------
__device__ __align__(16) __half g_Whi[NTOT * KTOT];   // permuted [n'][k], fp16-rounded
__device__ __align__(16) __half g_xhi[SS * BB * II];  // [s][b][i], fp16
__device__ __align__(16) __half g_hhi[2][BB * HH];    // h state, fp16
__device__ float g_bias[NTOT];

// producer counters: g_prod[grp][hchunk] (hchunk = 128 h-cols), cumulative.
__device__ unsigned g_prod[2][8];
__device__ unsigned g_fin;

// ------------------------------------------------------------------
// PTX helpers (baseline compute_103 features only)
// ------------------------------------------------------------------
__device__ __forceinline__ uint32_t smem_u32(const void* p) {
    uint32_t a;
    asm("{ .reg .u64 t; cvta.to.shared.u64 t, %1; cvt.u32.u64 %0, t; }"
        : "=r"(a) : "l"(p));
    return a;
}
__device__ __forceinline__ void cp_async16(uint32_t saddr, const void* gaddr) {
    asm volatile("cp.async.cg.shared.global [%0], [%1], 16;"
                 :: "r"(saddr), "l"(gaddr) : "memory");
}
__device__ __forceinline__ void cp_commit() {
    asm volatile("cp.async.commit_group;" ::: "memory");
}
__device__ __forceinline__ void cp_wait1() {
    asm volatile("cp.async.wait_group 1;" ::: "memory");
}
__device__ __forceinline__ void cp_wait0() {
    asm volatile("cp.async.wait_group 0;" ::: "memory");
}
__device__ __forceinline__ void ldsm_x4(uint32_t* r, uint32_t addr) {
    asm volatile("ldmatrix.sync.aligned.m8n8.x4.shared.b16 {%0,%1,%2,%3}, [%4];"
                 : "=r"(r[0]), "=r"(r[1]), "=r"(r[2]), "=r"(r[3]) : "r"(addr));
}
__device__ __forceinline__ void mma16816(float* d, const uint32_t* a,
                                         uint32_t b0, uint32_t b1) {
    asm volatile(
        "mma.sync.aligned.m16n8k16.row.col.f32.f16.f16.f32 "
        "{%0,%1,%2,%3}, {%4,%5,%6,%7}, {%8,%9}, {%0,%1,%2,%3};"
        : "+f"(d[0]), "+f"(d[1]), "+f"(d[2]), "+f"(d[3])
        : "r"(a[0]), "r"(a[1]), "r"(a[2]), "r"(a[3]), "r"(b0), "r"(b1));
}
__device__ __forceinline__ unsigned ld_acq(const unsigned* p) {
    unsigned v;
    asm volatile("ld.acquire.gpu.global.u32 %0, [%1];"
                 : "=r"(v) : "l"(p) : "memory");
    return v;
}
__device__ __forceinline__ void red_release_add(unsigned* p, unsigned v) {
    asm volatile("red.release.gpu.global.add.u32 [%0], %1;"
                 :: "l"(p), "r"(v) : "memory");
}
// fast activations (MUFU-based); rel err ~1e-6, budget is 1e-3
__device__ __forceinline__ float sigmoidf_(float v) {
    return __fdividef(1.0f, 1.0f + __expf(-v));
}
__device__ __forceinline__ float tanhf_(float v) {
    return 1.0f - __fdividef(2.0f, 1.0f + __expf(2.0f * v));
}
// swizzled smem byte offset within a [rows][64 half] sub-tile (128B rows)
__device__ __forceinline__ uint32_t sw_off(int r, int c) {   // c = 16B chunk 0..7
    return (uint32_t)(r * 128 + ((c ^ (r & 7)) << 4));
}

// ------------------------------------------------------------------
// Prep kernels
// ------------------------------------------------------------------
__global__ void prep_weights(const float* __restrict__ W_ih,
                             const float* __restrict__ W_hh) {
    int idx = blockIdx.x * blockDim.x + threadIdx.x;
    if (idx >= NTOT * KTOT) return;
    int n = idx / KTOT;
    int k = idx - n * KTOT;
    int nb = n >> 6;
    int r6 = n & 63;
    int wn = r6 >> 5;
    int g = (r6 >> 3) & 3;
    int jj = r6 & 7;
    int row = g * HH + nb * 16 + wn * 8 + jj;
    float v = (k < HH) ? W_hh[row * HH + k] : W_ih[row * II + (k - HH)];
    g_Whi[idx] = __float2half_rn(v);
}

__global__ void prep_x(const float* __restrict__ x) {
    int idx = blockIdx.x * blockDim.x + threadIdx.x;
    if (idx >= SS * BB * II) return;
    int s = idx / (BB * II);
    int r = idx - s * (BB * II);
    int b = r / II;
    int i = r - b * II;
    g_xhi[idx] = __float2half_rn(x[(b * SS + s) * II + i]);
}

__global__ void prep_state(const float* __restrict__ h0,
                           const float* __restrict__ b_ih,
                           const float* __restrict__ b_hh) {
    int idx = blockIdx.x * blockDim.x + threadIdx.x;
    if (idx < BB * HH)
        g_hhi[0][idx] = __float2half_rn(h0[idx]);
    if (idx < NTOT) g_bias[idx] = b_ih[idx] + b_hh[idx];
}

// ------------------------------------------------------------------
// Persistent LSTM kernel: all 512 steps. R16 structure, single-term:
//   gates = h_fp16 * W_fp16  (fp32 accumulate; c stays fp32 in regs)
// 4 MMAs + 3 LDSM per k-step (was 8 + 4).
// ------------------------------------------------------------------
__global__ void __launch_bounds__(NTHREADS, 1) lstm_persistent(
    const float* __restrict__ c0in)
{
    extern __shared__ char smem_raw[];
    const uint32_t sb = smem_u32(smem_raw);

    const int tid = threadIdx.x;
    const int wid = tid >> 5;
    const int lane = tid & 31;
    const int grp = blockIdx.x & 1;        // batch group (rows grp*64..+63)
    const int nb = blockIdx.x >> 1;        // n-tile index (0..63)
    const int gb = grp * CTA_M;            // global batch base
    const int off = nb >> 3;               // own h-chunk first (producer = nb>>3)
    const int wm = wid & 3;                // 0..3 : M warp group (16 rows)
    const int wn = wid >> 2;               // 0..1 : N warp group (32 cols)
    const int frow = lane >> 2;            // fragment row 0..7
    const int fcol = (lane & 3) * 2;       // fragment col (even)
    const int b0 = gb + wm * 16 + frow;
    const int jbw = nb * 16 + wn * 8;      // h-column base for this warp

    float bias_r[4][2];
#pragma unroll
    for (int g = 0; g < 4; g++)
#pragma unroll
        for (int e = 0; e < 2; e++)
            bias_r[g][e] = g_bias[g * HH + jbw + fcol + e];

    float creg[4];
    creg[0] = c0in[b0 * HH + jbw + fcol];
    creg[1] = c0in[b0 * HH + jbw + fcol + 1];
    creg[2] = c0in[(b0 + 8) * HH + jbw + fcol];
    creg[3] = c0in[(b0 + 8) * HH + jbw + fcol + 1];

    // stage loader: ci 0,1 -> x chunks (ka 8,9) of step ss;
    //               ci 2..9 -> h chunks of step ss, ka=((ci-2)+off)&7
    auto load_stage = [&](int ci, int ss) {
        const uint32_t st = sb + (uint32_t)(ci % NSTAGE) * STAGE_BYTES;
        const int ka = (ci < 2) ? (8 + ci) : (((ci - 2) + off) & 7);
        const int k0 = ka * KC;
        const __half* __restrict__ hin = g_hhi[ss & 1];
#pragma unroll
        for (int i = 0; i < 4; i++) {           // A: 64 x 128 halves
            int id = tid + i * NTHREADS;        // 0..1023
            int r = id >> 4;                    // local batch row 0..63
            int c = id & 15;                    // 16B chunk in 256B row
            uint32_t d = (uint32_t)((c >> 3) * 8192) + sw_off(r, c & 7);
            if (ka < 8) {
                cp_async16(st + ST_AH + d, hin + (gb + r) * HH + k0 + c * 8);
            } else {
                size_t o = ((size_t)ss * BB + gb + r) * II + (k0 - HH) + c * 8;
                cp_async16(st + ST_AH + d, g_xhi + o);
            }
        }
#pragma unroll
        for (int i = 0; i < 4; i++) {           // B: 64 x 128 halves
            int id = tid + i * NTHREADS;
            int r = id >> 4;
            int c = id & 15;
            uint32_t d = (uint32_t)((c >> 3) * 8192) + sw_off(r, c & 7);
            size_t o = (size_t)(nb * CTA_N + r) * KTOT + k0 + c * 8;
            cp_async16(st + ST_BH + d, g_Whi + o);
        }
        cp_commit();
    };

    // prologue for step 0: x chunks (h0 published by prep, stream-ordered)
    load_stage(0, 0);
    load_stage(1, 0);

    for (int s = 0; s < SS; s++) {
        __half* __restrict__ hout = g_hhi[(s & 1) ^ 1];

        // all-thread acquire spin before reading an h-chunk of step s
        auto poll_chunk = [&](int ci) {
            if (s > 0) {
                const int ka = ((ci - 2) + off) & 7;
                const unsigned tgt = 8u * (unsigned)s;
                const unsigned* ctr = &g_prod[grp][ka];
                while (ld_acq(ctr) < tgt) __nanosleep(32);
            }
        };

        float acc[4][4];
#pragma unroll
        for (int g = 0; g < 4; g++)
#pragma unroll
            for (int e = 0; e < 4; e++) acc[g][e] = 0.0f;

        for (int i = 0; i < NCHUNK; i++) {
            if (i == NCHUNK - 1) cp_wait0(); else cp_wait1();
            __syncthreads();               // the ONLY barrier per chunk

            const uint32_t st = sb + (uint32_t)(i % NSTAGE) * STAGE_BYTES;
#pragma unroll
            for (int kk = 0; kk < KC; kk += 16) {
                const uint32_t subo = (uint32_t)((kk >> 6) * 8192);
                const int ck = (((kk & 63) >> 3)) + (lane >> 4);
                const int ra = wm * 16 + (lane & 15);
                const int rb = wn * 32 + (lane & 15);
                uint32_t ah[4], bh0[4], bh1[4];
                ldsm_x4(ah, st + ST_AH + subo + sw_off(ra, ck));
                ldsm_x4(bh0, st + ST_BH + subo + sw_off(rb, ck));
                ldsm_x4(bh1, st + ST_BH + subo + sw_off(rb + 16, ck));

                mma16816(acc[0], ah, bh0[0], bh0[2]);
                mma16816(acc[1], ah, bh0[1], bh0[3]);
                mma16816(acc[2], ah, bh1[0], bh1[2]);
                mma16816(acc[3], ah, bh1[1], bh1[3]);
            }

            // issue next chunk's loads (spin stalls only this thread's issue)
            if (i + 2 < NCHUNK) {
                poll_chunk(i + 2);         // i+2 >= 2: always an h-chunk
                load_stage(i + 2, s);
            }
        }

        // ---- prefetch next step's x chunks while epilogue computes ----
        if (s + 1 < SS) {
            load_stage(0, s + 1);
            load_stage(1, s + 1);
        }

        // ---- register-only LSTM cell update ----
#pragma unroll
        for (int e = 0; e < 4; e++) {
            float iv = acc[0][e] + bias_r[0][e & 1];
            float fv = acc[1][e] + bias_r[1][e & 1];
            float gv = acc[2][e] + bias_r[2][e & 1];
            float ov = acc[3][e] + bias_r[3][e & 1];
            float ig = sigmoidf_(iv);
            float fg = sigmoidf_(fv);
            float gg = tanhf_(gv);
            float og = sigmoidf_(ov);
            float cn = fg * creg[e] + ig * gg;
            creg[e] = cn;
            float hn = og * tanhf_(cn);
            int b = b0 + ((e >> 1) << 3);
            hout[b * HH + jbw + fcol + (e & 1)] = __float2half_rn(hn);
        }

        // ---- publish: release-atomic arrive on this CTA's h-chunk ----
        __syncthreads();                 // all h stores of this CTA done
        if (tid == 0) {
            red_release_add(&g_prod[grp][nb >> 3], 1u);
        }
    }

    // ---- finish: reset counters for the next graph replay ----
    if (tid == 0) {
        __threadfence();
        atomicAdd(&g_fin, 1u);
    }
    if (blockIdx.x == 0 && tid == 0) {
        while (ld_acq(&g_fin) < (unsigned)NCTA) __nanosleep(64);
#pragma unroll
        for (int g2 = 0; g2 < 2; g2++)
#pragma unroll
            for (int kc = 0; kc < 8; kc++)
                *((volatile unsigned*)&g_prod[g2][kc]) = 0u;
        *((volatile unsigned*)&g_fin) = 0u;
        __threadfence();
    }
}

// ------------------------------------------------------------------
// Head: out[b,c] = h_last . W_out[c] + b_out[c]
// ------------------------------------------------------------------
__global__ void head_kernel(const float* __restrict__ W_out,
                            const float* __restrict__ b_out,
                            float* __restrict__ out) {
    int b = blockIdx.x;
    int c = blockIdx.y;
    int lane = threadIdx.x;
    const __half* hh = g_hhi[0] + b * HH;   // 512 steps even -> buffer 0
    const float* w = W_out + c * HH;
    float sum = 0.0f;
    for (int k = lane; k < HH; k += 32)
        sum = fmaf(__half2float(hh[k]), w[k], sum);
#pragma unroll
    for (int off = 16; off > 0; off >>= 1)
        sum += __shfl_down_sync(0xFFFFFFFFu, sum, off);
    if (lane == 0) out[b * NC + c] = sum + b_out[c];
}

// ------------------------------------------------------------------
// Host
// ------------------------------------------------------------------
extern "C" void kernel_launch(void* const* d_in, const int* in_sizes, int n_in,
                              void* d_out, int out_size) {
    const float* x     = (const float*)d_in[0];
    const float* h0    = (const float*)d_in[1];
    const float* c0    = (const float*)d_in[2];
    const float* W_ih  = (const float*)d_in[3];
    const float* W_hh  = (const float*)d_in[4];
    const float* b_ih  = (const float*)d_in[5];
    const float* b_hh  = (const float*)d_in[6];
    const float* W_out = (const float*)d_in[7];
    const float* b_out = (const float*)d_in[8];
    float* out = (float*)d_out;

    cudaFuncSetAttribute(lstm_persistent,
                         cudaFuncAttributeMaxDynamicSharedMemorySize, SMEM_NEED);

    prep_weights<<<(NTOT * KTOT + 255) / 256, 256>>>(W_ih, W_hh);
    prep_x<<<(SS * BB * II + 255) / 256, 256>>>(x);
    prep_state<<<(BB * HH + 255) / 256, 256>>>(h0, b_ih, b_hh);

    lstm_persistent<<<NCTA, NTHREADS, SMEM_NEED>>>(c0);

    head_kernel<<<dim3(BB, NC), 32>>>(W_out, b_out, out);
}